// round 4
// baseline (speedup 1.0000x reference)
#include <cuda_runtime.h>

#define NN 10
#define MM 22
#define RR 2
#define NPAIR 55
#define TPB 160          // 5 warps: warp g handles rows {g, 9-g} for 32 batches
#define BPB 32           // batches per block

typedef unsigned long long u64;

__device__ __forceinline__ u64 pack2(float x, float y) {
    u64 r; asm("mov.b64 %0, {%1, %2};" : "=l"(r) : "f"(x), "f"(y)); return r;
}
__device__ __forceinline__ void unpack2(u64 v, float& x, float& y) {
    asm("mov.b64 {%0, %1}, %2;" : "=f"(x), "=f"(y) : "l"(v));
}
__device__ __forceinline__ u64 fma2(u64 a, u64 b, u64 c) {
    u64 d; asm("fma.rn.f32x2 %0, %1, %2, %3;" : "=l"(d) : "l"(a), "l"(b), "l"(c)); return d;
}
__device__ __forceinline__ u64 mul2(u64 a, u64 b) {
    u64 d; asm("mul.rn.f32x2 %0, %1, %2;" : "=l"(d) : "l"(a), "l"(b)); return d;
}
__device__ __forceinline__ u64 one2() { return 0x3f8000003f800000ULL; }

__global__ void __launch_bounds__(TPB)
tl_kernel(const float* __restrict__ pred,   // (B, M)
          const float* __restrict__ sel,    // (N, N, R, M, 3)
          const float* __restrict__ alog,   // (N, N, R)
          float* __restrict__ out,          // (B, N, N)
          int B) {
    __shared__ ulonglong2 sh[NPAIR][MM];        // packed coefficients  (19.4 KB)
    __shared__ float shw[TPB][13];              // per-thread w scratch (8.3 KB, pad 13)
    __shared__ float otile[BPB][101];           // output staging       (12.9 KB, pad 101)

    // ---- Build coefficient table (same in every block; 8 strided iters/thread) ----
    for (int idx = threadIdx.x; idx < NPAIR * MM; idx += TPB) {
        int p = idx / MM, m = idx - p * MM;
        int i = 0, rem = p;
        while (rem >= NN - i) { rem -= NN - i; i++; }
        int j = i + rem;
        float Av[RR], Bv[RR];
#pragma unroll
        for (int r = 0; r < RR; r++) {
            const float* s = sel + (size_t)((((i * NN + j) * RR + r) * MM + m) * 3);
            float x0 = s[0] * 1.25f, x1 = s[1] * 1.25f, x2 = s[2] * 1.25f;  // /LIT_TEMP
            float mx = fmaxf(x0, fmaxf(x1, x2));
            float e0 = __expf(x0 - mx), e1 = __expf(x1 - mx), e2 = __expf(x2 - mx);
            float inv = 1.0f / (e0 + e1 + e2);
            float s0 = e0 * inv, s1 = e1 * inv, s2 = e2 * inv;
            float A = s0 + s2, Bc = s1 - s2;
            if (m == 0) {   // fold alpha = sigmoid(alog) into the first literal
                float a = alog[(i * NN + j) * RR + r];
                float alpha = 1.0f / (1.0f + __expf(-a));
                A *= alpha; Bc *= alpha;
            }
            Av[r] = A; Bv[r] = Bc;
        }
        ulonglong2 v;
        v.x = pack2(Av[0], Av[1]);
        v.y = pack2(Bv[0], Bv[1]);
        sh[p][m] = v;
    }
    __syncthreads();

    const int lane = threadIdx.x & 31;
    const int g    = threadIdx.x >> 5;        // warp id 0..4 = row group
    const int b    = blockIdx.x * BPB + lane; // batch handled by this lane

    if (b < B) {
        // ---- Load u (22 floats), pre-duplicated into packed f32x2 regs ----
        u64 u2[MM];
        const float2* up = reinterpret_cast<const float2*>(pred + (size_t)b * MM);
#pragma unroll
        for (int k = 0; k < MM / 2; k++) {
            float2 t = __ldg(up + k);
            u2[2 * k]     = pack2(t.x, t.x);
            u2[2 * k + 1] = pack2(t.y, t.y);
        }

        float* wbuf = shw[threadIdx.x];
        // ---- Two rows per thread: i = g and i = 9-g (11 pairs total, balanced) ----
#pragma unroll 1
        for (int rr = 0; rr < 2; rr++) {
            int i  = (rr == 0) ? g : (NN - 1 - g);
            int pb = i * NN - (i * (i - 1)) / 2;       // row start: pair (i,i) index
            int np = NN - i;
            float rsum = 0.0f;
#pragma unroll 1
            for (int jj = 0; jj < np; jj++) {
                const ulonglong2* cp = sh[pb + jj];
                u64 accA = one2(), accB = one2();      // two chains (even/odd m) for ILP
#pragma unroll
                for (int m = 0; m < MM; m += 2) {
                    ulonglong2 c0 = cp[m];
                    ulonglong2 c1 = cp[m + 1];
                    accA = mul2(accA, fma2(c0.y, u2[m],     c0.x));  // lit = B*u + A (both r)
                    accB = mul2(accB, fma2(c1.y, u2[m + 1], c1.x));
                }
                float c0f, c1f;
                unpack2(mul2(accA, accB), c0f, c1f);   // c_r = alpha_r * clause_r
                float gg = c0f + c1f - c0f * c1f;      // 1 - (1-c0)(1-c1)
                float gc = fmaxf(gg, 1e-6f);
                float w  = gc * gc;                    // exp(log(g)/0.5) == g^2
                wbuf[jj] = w;
                rsum += w;
            }
            float rinv = 1.0f / rsum;
            float* orow = &otile[lane][i * NN];
#pragma unroll 1
            for (int j = 0; j < i; j++) orow[j] = 0.0f;
#pragma unroll 1
            for (int jj = 0; jj < np; jj++) orow[i + jj] = wbuf[jj] * rinv;
        }
    }
    __syncthreads();

    // ---- Coalesced write-out of the block's 32x100 tile ----
    int bmax = B - blockIdx.x * BPB;              // batches in this block
    int emax = (bmax >= BPB ? BPB : bmax) * (NN * NN);
    float* ob = out + (size_t)blockIdx.x * (BPB * NN * NN);
#pragma unroll 1
    for (int e = threadIdx.x; e < emax; e += TPB) {
        int bb = e / 100, c = e - bb * 100;
        ob[e] = otile[bb][c];
    }
}

extern "C" void kernel_launch(void* const* d_in, const int* in_sizes, int n_in,
                              void* d_out, int out_size) {
    const float* pred = (const float*)d_in[0];   // (B, M)
    const float* sel  = (const float*)d_in[1];   // (N, N, R, M, 3)
    const float* alog = (const float*)d_in[2];   // (N, N, R)
    float* out = (float*)d_out;                  // (B, N, N)
    int B = in_sizes[0] / MM;
    int blocks = (B + BPB - 1) / BPB;            // 32 batches per 160-thread block
    tl_kernel<<<blocks, TPB>>>(pred, sel, alog, out, B);
}

// round 5
// speedup vs baseline: 1.1137x; 1.1137x over previous
#include <cuda_runtime.h>

#define NN 10
#define MM 22
#define RR 2
#define NPAIR 55
#define TPB 352     // 11 warps x 5 pairs = 55 pairs, exact balance
#define BPB 32      // batches per block (one per lane)

typedef unsigned long long u64;

__device__ ulonglong2 gcoef[NPAIR][MM];   // packed (A_r0,A_r1 | B_r0,B_r1), alpha folded at m==0

__constant__ int PAIR_CELL[NPAIR] = {
  0,1,2,3,4,5,6,7,8,9,
  11,12,13,14,15,16,17,18,19,
  22,23,24,25,26,27,28,29,
  33,34,35,36,37,38,39,
  44,45,46,47,48,49,
  55,56,57,58,59,
  66,67,68,69,
  77,78,79,
  88,89,
  99};

__device__ __forceinline__ u64 pack2(float x, float y) {
    u64 r; asm("mov.b64 %0, {%1, %2};" : "=l"(r) : "f"(x), "f"(y)); return r;
}
__device__ __forceinline__ void unpack2(u64 v, float& x, float& y) {
    asm("mov.b64 {%0, %1}, %2;" : "=f"(x), "=f"(y) : "l"(v));
}
__device__ __forceinline__ u64 fma2(u64 a, u64 b, u64 c) {
    u64 d; asm("fma.rn.f32x2 %0, %1, %2, %3;" : "=l"(d) : "l"(a), "l"(b), "l"(c)); return d;
}
__device__ __forceinline__ u64 mul2(u64 a, u64 b) {
    u64 d; asm("mul.rn.f32x2 %0, %1, %2;" : "=l"(d) : "l"(a), "l"(b)); return d;
}
__device__ __forceinline__ u64 one2() { return 0x3f8000003f800000ULL; }

// ---- One-shot coefficient build: softmax over literal selectors + alpha fold ----
__global__ void tl_build(const float* __restrict__ sel, const float* __restrict__ alog) {
    int idx = blockIdx.x * blockDim.x + threadIdx.x;
    if (idx >= NPAIR * MM) return;
    int p = idx / MM, m = idx - p * MM;
    int i = 0, rem = p;
    while (rem >= NN - i) { rem -= NN - i; i++; }
    int j = i + rem;
    float Av[RR], Bv[RR];
#pragma unroll
    for (int r = 0; r < RR; r++) {
        const float* s = sel + (size_t)((((i * NN + j) * RR + r) * MM + m) * 3);
        float x0 = s[0] * 1.25f, x1 = s[1] * 1.25f, x2 = s[2] * 1.25f;  // /LIT_TEMP
        float mx = fmaxf(x0, fmaxf(x1, x2));
        float e0 = __expf(x0 - mx), e1 = __expf(x1 - mx), e2 = __expf(x2 - mx);
        float inv = 1.0f / (e0 + e1 + e2);
        float s0 = e0 * inv, s1 = e1 * inv, s2 = e2 * inv;
        float A = s0 + s2, Bc = s1 - s2;      // lit = A + B*u
        if (m == 0) {                          // fold alpha = sigmoid(alog)
            float a = alog[(i * NN + j) * RR + r];
            float alpha = 1.0f / (1.0f + __expf(-a));
            A *= alpha; Bc *= alpha;
        }
        Av[r] = A; Bv[r] = Bc;
    }
    ulonglong2 v;
    v.x = pack2(Av[0], Av[1]);
    v.y = pack2(Bv[0], Bv[1]);
    gcoef[p][m] = v;
}

// ---- Main kernel: pure hot loop + normalize + coalesced store ----
__global__ void __launch_bounds__(TPB, 3)
tl_main(const float* __restrict__ pred,   // (B, M)
        float* __restrict__ out,          // (B, N, N)
        int B) {
    __shared__ ulonglong2 sh[NPAIR][MM];   // 19.4 KB coefficients
    __shared__ float wtile[BPB][101];      // 12.9 KB per-block output tile (pad 101: conflict-free)

    // Copy coefficient table to smem (1210 x 16B, ~3.5 iters/thread)
    {
        const ulonglong2* gsrc = &gcoef[0][0];
        ulonglong2* sdst = &sh[0][0];
        for (int idx = threadIdx.x; idx < NPAIR * MM; idx += TPB) sdst[idx] = gsrc[idx];
    }
    __syncthreads();

    const int lane = threadIdx.x & 31;
    const int w    = threadIdx.x >> 5;           // warp id 0..10
    const int b    = blockIdx.x * BPB + lane;    // batch for this lane

    // Load u, pre-duplicated into packed f32x2 registers
    u64 u2[MM];
    if (b < B) {
        const float2* up = reinterpret_cast<const float2*>(pred + (size_t)b * MM);
#pragma unroll
        for (int k = 0; k < MM / 2; k++) {
            float2 t = __ldg(up + k);
            u2[2 * k]     = pack2(t.x, t.x);
            u2[2 * k + 1] = pack2(t.y, t.y);
        }
    } else {
#pragma unroll
        for (int m = 0; m < MM; m++) u2[m] = 0;
    }

    // ---- Phase 1: each warp computes 5 clause-pairs for its 32 batches ----
    const int p0 = w * 5;
#pragma unroll 1
    for (int k = 0; k < 5; k++) {
        const ulonglong2* cp = sh[p0 + k];
        u64 accA = one2(), accB = one2();        // even/odd m chains for ILP
#pragma unroll
        for (int m = 0; m < MM; m += 2) {
            ulonglong2 c0 = cp[m];
            ulonglong2 c1 = cp[m + 1];
            accA = mul2(accA, fma2(c0.y, u2[m],     c0.x));   // lit = B*u + A (both r)
            accB = mul2(accB, fma2(c1.y, u2[m + 1], c1.x));
        }
        float c0f, c1f;
        unpack2(mul2(accA, accB), c0f, c1f);     // c_r = alpha_r * clause_r
        float gg = c0f + c1f - c0f * c1f;        // 1 - (1-c0)(1-c1)
        float gc = fmaxf(gg, 1e-6f);
        wtile[lane][PAIR_CELL[p0 + k]] = gc * gc;  // exp(log(g)/0.5) == g^2
    }
    __syncthreads();

    // ---- Phase 2: warps 0..9 normalize row w for 32 batches; zero lower triangle ----
    if (w < NN) {
        float* cells = &wtile[lane][w * NN];
        float s = 0.0f;
#pragma unroll 1
        for (int j = w; j < NN; j++) s += cells[j];
        float rinv = 1.0f / s;
#pragma unroll
        for (int j = 0; j < NN; j++) cells[j] = (j >= w) ? cells[j] * rinv : 0.0f;
    }
    __syncthreads();

    // ---- Phase 3: coalesced write-out of the 32x100 tile ----
    int bmax = B - blockIdx.x * BPB;
    if (bmax > BPB) bmax = BPB;
    int emax = bmax * (NN * NN);
    float* ob = out + (size_t)blockIdx.x * (BPB * NN * NN);
#pragma unroll 1
    for (int e = threadIdx.x; e < emax; e += TPB) {
        int bb = e / 100, c = e - bb * 100;
        ob[e] = wtile[bb][c];
    }
}

extern "C" void kernel_launch(void* const* d_in, const int* in_sizes, int n_in,
                              void* d_out, int out_size) {
    const float* pred = (const float*)d_in[0];   // (B, M)
    const float* sel  = (const float*)d_in[1];   // (N, N, R, M, 3)
    const float* alog = (const float*)d_in[2];   // (N, N, R)
    float* out = (float*)d_out;                  // (B, N, N)
    int B = in_sizes[0] / MM;
    tl_build<<<10, 128>>>(sel, alog);            // 1210 entries, one-shot
    int blocks = (B + BPB - 1) / BPB;            // 512 blocks of 352 threads
    tl_main<<<blocks, TPB>>>(pred, out, B);
}

// round 7
// speedup vs baseline: 1.2381x; 1.1117x over previous
#include <cuda_runtime.h>

#define NN 10
#define MM 22
#define RR 2
#define NPAIR 55
#define TPB 160     // 5 warps: warp g owns rows {g, 9-g} = 11 pairs, exact balance
#define BPB 32      // batches per block (one per lane)

typedef unsigned long long u64;

__device__ ulonglong2 gcoef[NPAIR][MM];   // packed (A_r0,A_r1 | B_r0,B_r1), alpha folded at m==0

__device__ __forceinline__ u64 pack2(float x, float y) {
    u64 r; asm("mov.b64 %0, {%1, %2};" : "=l"(r) : "f"(x), "f"(y)); return r;
}
__device__ __forceinline__ void unpack2(u64 v, float& x, float& y) {
    asm("mov.b64 {%0, %1}, %2;" : "=f"(x), "=f"(y) : "l"(v));
}
__device__ __forceinline__ u64 fma2(u64 a, u64 b, u64 c) {
    u64 d; asm("fma.rn.f32x2 %0, %1, %2, %3;" : "=l"(d) : "l"(a), "l"(b), "l"(c)); return d;
}
__device__ __forceinline__ u64 mul2(u64 a, u64 b) {
    u64 d; asm("mul.rn.f32x2 %0, %1, %2;" : "=l"(d) : "l"(a), "l"(b)); return d;
}
__device__ __forceinline__ u64 one2() { return 0x3f8000003f800000ULL; }

// ---- One-shot coefficient build: softmax over literal selectors + alpha fold ----
__global__ void tl_build(const float* __restrict__ sel, const float* __restrict__ alog) {
    int idx = blockIdx.x * blockDim.x + threadIdx.x;
    if (idx >= NPAIR * MM) return;
    int p = idx / MM, m = idx - p * MM;
    int i = 0, rem = p;
    while (rem >= NN - i) { rem -= NN - i; i++; }
    int j = i + rem;
    float Av[RR], Bv[RR];
#pragma unroll
    for (int r = 0; r < RR; r++) {
        const float* s = sel + (size_t)((((i * NN + j) * RR + r) * MM + m) * 3);
        float x0 = s[0] * 1.25f, x1 = s[1] * 1.25f, x2 = s[2] * 1.25f;  // /LIT_TEMP
        float mx = fmaxf(x0, fmaxf(x1, x2));
        float e0 = __expf(x0 - mx), e1 = __expf(x1 - mx), e2 = __expf(x2 - mx);
        float inv = 1.0f / (e0 + e1 + e2);
        float s0 = e0 * inv, s1 = e1 * inv, s2 = e2 * inv;
        float A = s0 + s2, Bc = s1 - s2;       // lit = A + B*u
        if (m == 0) {                           // fold alpha = sigmoid(alog)
            float a = alog[(i * NN + j) * RR + r];
            float alpha = 1.0f / (1.0f + __expf(-a));
            A *= alpha; Bc *= alpha;
        }
        Av[r] = A; Bv[r] = Bc;
    }
    ulonglong2 v;
    v.x = pack2(Av[0], Av[1]);
    v.y = pack2(Bv[0], Bv[1]);
    gcoef[p][m] = v;
}

// ---- Main kernel ----
__global__ void __launch_bounds__(TPB)
tl_main(const float* __restrict__ pred,   // (B, M)
        float* __restrict__ out,          // (B, N, N)
        int B) {
    __shared__ ulonglong2 sh[NPAIR][MM];   // 19.4 KB coefficients
    __shared__ float wtile[BPB][101];      // 12.9 KB raw w tile (pad 101: conflict-free)
    __shared__ float rinvt[BPB][11];       // 1.4 KB per-(batch,row) 1/rowsum
    __shared__ float psm[BPB][MM + 1];     // 2.9 KB staged pred (pad 23: conflict-free reads)

    // Coefficient table gmem -> smem (coalesced LDG.128)
    {
        const ulonglong2* gsrc = &gcoef[0][0];
        ulonglong2* sdst = &sh[0][0];
        for (int idx = threadIdx.x; idx < NPAIR * MM; idx += TPB) sdst[idx] = gsrc[idx];
    }
    // Stage this block's 32x22 pred slab, coalesced
    {
        const float* gp = pred + (size_t)blockIdx.x * BPB * MM;
        int nelem = BPB * MM;
        int gmax = B * MM - blockIdx.x * BPB * MM;    // guard for last block
        if (nelem > gmax) nelem = gmax;
        for (int t = threadIdx.x; t < nelem; t += TPB) {
            int bb = t / MM, m = t - bb * MM;
            psm[bb][m] = __ldg(gp + t);
        }
    }
    __syncthreads();

    const int lane = threadIdx.x & 31;
    const int g    = threadIdx.x >> 5;           // warp id 0..4

    // u from smem, duplicated into packed f32x2 regs (conflict-free: stride 23)
    u64 u2[MM];
#pragma unroll
    for (int m = 0; m < MM; m++) {
        float v = psm[lane][m];
        u2[m] = pack2(v, v);
    }

    // ---- Phase 1: warp g computes full rows i = g and i = 9-g ----
#pragma unroll 1
    for (int rr = 0; rr < 2; rr++) {
        int i  = (rr == 0) ? g : (NN - 1 - g);
        int pb = i * NN - (i * (i - 1)) / 2;     // first pair (i,i) index
        int np = NN - i;
        float rsum = 0.0f;
        float* wrow = &wtile[lane][i * NN + i];
#pragma unroll 1
        for (int jj = 0; jj < np; jj++) {
            const ulonglong2* cp = sh[pb + jj];
            u64 a0 = one2(), a1 = one2(), a2 = one2(), a3 = one2();  // 4 chains for ILP
#pragma unroll
            for (int m = 0; m < 20; m += 4) {
                ulonglong2 c0 = cp[m],     c1 = cp[m + 1];
                ulonglong2 c2 = cp[m + 2], c3 = cp[m + 3];
                a0 = mul2(a0, fma2(c0.y, u2[m],     c0.x));   // lit = B*u + A (both r)
                a1 = mul2(a1, fma2(c1.y, u2[m + 1], c1.x));
                a2 = mul2(a2, fma2(c2.y, u2[m + 2], c2.x));
                a3 = mul2(a3, fma2(c3.y, u2[m + 3], c3.x));
            }
            {
                ulonglong2 c0 = cp[20], c1 = cp[21];
                a0 = mul2(a0, fma2(c0.y, u2[20], c0.x));
                a1 = mul2(a1, fma2(c1.y, u2[21], c1.x));
            }
            float c0f, c1f;
            unpack2(mul2(mul2(a0, a1), mul2(a2, a3)), c0f, c1f);  // c_r = alpha_r*clause_r
            float gg = c0f + c1f - c0f * c1f;     // 1 - (1-c0)(1-c1)
            float gc = fmaxf(gg, 1e-6f);
            float w  = gc * gc;                   // exp(log(g)/0.5) == g^2
            wrow[jj] = w;
            rsum += w;
        }
        rinvt[lane][i] = 1.0f / rsum;             // each row slot written by exactly one warp
    }
    __syncthreads();

    // ---- Phase 2: coalesced, normalized write-out with lower-triangle zeros ----
    int bmax = B - blockIdx.x * BPB;
    if (bmax > BPB) bmax = BPB;
    int emax = bmax * (NN * NN);
    float* ob = out + (size_t)blockIdx.x * (BPB * NN * NN);
#pragma unroll 1
    for (int e = threadIdx.x; e < emax; e += TPB) {
        int bb  = e / 100, c = e - bb * 100;
        int row = c / 10,  col = c - row * 10;
        float v = (col >= row) ? wtile[bb][c] * rinvt[bb][row] : 0.0f;
        ob[e] = v;
    }
}

extern "C" void kernel_launch(void* const* d_in, const int* in_sizes, int n_in,
                              void* d_out, int out_size) {
    const float* pred = (const float*)d_in[0];   // (B, M)
    const float* sel  = (const float*)d_in[1];   // (N, N, R, M, 3)
    const float* alog = (const float*)d_in[2];   // (N, N, R)
    float* out = (float*)d_out;                  // (B, N, N)
    int B = in_sizes[0] / MM;
    tl_build<<<10, 128>>>(sel, alog);            // 1210 entries, one-shot
    int blocks = (B + BPB - 1) / BPB;            // 512 blocks of 160 threads, single wave
    tl_main<<<blocks, TPB>>>(pred, out, B);
}